// round 17
// baseline (speedup 1.0000x reference)
#include <cuda_runtime.h>
#include <cuda_fp16.h>
#include <cstdint>

#define MAX_N 100000
#define MAX_E 1600000
#define F 128
#define SCAN_CHUNK 512
#define MAX_BLK ((MAX_N + SCAN_CHUNK - 1) / SCAN_CHUNK)

// Scratch (__device__ globals; no allocations allowed)
__device__ __half2 g_h16[(size_t)MAX_N * (F / 2)];  // x@W (UNscaled), fp16
__device__ float g_dinv[MAX_N];
__device__ float g_ecoef[MAX_E];          // dinv[src], dst-sorted order
__device__ int   g_cnt[MAX_N];
__device__ int   g_start[MAX_N];
__device__ int   g_cursor[MAX_N];
__device__ int   g_esrc[MAX_E];
__device__ int   g_bsum[MAX_BLK];
__device__ uint4 g_wf16[16 * 4 * 32];     // frag-ordered fp16 W (32KB)

// ---------------------------------------------------------------------------
__global__ void k_zero(int n) {
    int i = blockIdx.x * blockDim.x + threadIdx.x;
    if (i < n) g_cnt[i] = 0;
}

// int4-vectorized histogram over dst
__global__ void k_hist(const int* __restrict__ dst, int e) {
    int i = blockIdx.x * blockDim.x + threadIdx.x;
    int base = i * 4;
    if (base + 3 < e) {
        int4 d = *(const int4*)(dst + base);
        atomicAdd(&g_cnt[d.x], 1);
        atomicAdd(&g_cnt[d.y], 1);
        atomicAdd(&g_cnt[d.z], 1);
        atomicAdd(&g_cnt[d.w], 1);
    } else {
        for (int k = base; k < e; k++) atomicAdd(&g_cnt[dst[k]], 1);
    }
}

__global__ void k_scan1(int n) {
    __shared__ int wsum[16];
    int b = blockIdx.x;
    int i = b * SCAN_CHUNK + threadIdx.x;
    int v = (i < n) ? g_cnt[i] : 0;
    for (int o = 16; o > 0; o >>= 1) v += __shfl_down_sync(~0u, v, o);
    int lane = threadIdx.x & 31, wid = threadIdx.x >> 5;
    if (lane == 0) wsum[wid] = v;
    __syncthreads();
    if (wid == 0) {
        int s = (lane < (SCAN_CHUNK / 32)) ? wsum[lane] : 0;
        for (int o = 16; o > 0; o >>= 1) s += __shfl_down_sync(~0u, s, o);
        if (lane == 0) g_bsum[b] = s;
    }
}

// fused: every block re-scans all block sums locally, then does its own chunk.
// Also computes g_dinv.
__global__ void k_scan3(int n, int nblk) {
    __shared__ int wsum[16];
    __shared__ int sh_off;
    int b = blockIdx.x;
    int t = threadIdx.x;
    int lane = t & 31, wid = t >> 5;

    {
        int v = (t < nblk) ? g_bsum[t] : 0;
        int x = v;
        for (int o = 1; o < 32; o <<= 1) {
            int y = __shfl_up_sync(~0u, x, o);
            if (lane >= o) x += y;
        }
        if (lane == 31) wsum[wid] = x;
        __syncthreads();
        if (wid == 0) {
            int w = (lane < 16) ? wsum[lane] : 0;
            for (int o = 1; o < 16; o <<= 1) {
                int y = __shfl_up_sync(~0u, w, o);
                if (lane >= o) w += y;
            }
            if (lane < 16) wsum[lane] = w;
        }
        __syncthreads();
        int excl = x - v + (wid ? wsum[wid - 1] : 0);
        if (t == b) sh_off = excl;
        __syncthreads();
    }

    int i = b * SCAN_CHUNK + t;
    int v = (i < n) ? g_cnt[i] : 0;
    int x = v;
    for (int o = 1; o < 32; o <<= 1) {
        int y = __shfl_up_sync(~0u, x, o);
        if (lane >= o) x += y;
    }
    if (lane == 31) wsum[wid] = x;
    __syncthreads();
    if (wid == 0) {
        int w = (lane < 16) ? wsum[lane] : 0;
        for (int o = 1; o < 16; o <<= 1) {
            int y = __shfl_up_sync(~0u, w, o);
            if (lane >= o) w += y;
        }
        if (lane < 16) wsum[lane] = w;
    }
    __syncthreads();
    int excl = x - v + (wid ? wsum[wid - 1] : 0);
    if (i < n) {
        int s = excl + sh_off;
        g_start[i] = s;
        g_cursor[i] = s;
        g_dinv[i] = rsqrtf((float)(v + 1));
    }
}

// fill CSR: src index AND precomputed coefficient dinv[src]
__global__ void k_fill(const int* __restrict__ src, const int* __restrict__ dst,
                       int e) {
    int i = blockIdx.x * blockDim.x + threadIdx.x;
    if (i < e) {
        int s = src[i];
        int p = atomicAdd(&g_cursor[dst[i]], 1);
        g_esrc[p] = s;
        g_ecoef[p] = g_dinv[s];
    }
}

// ---------------------------------------------------------------------------
__device__ __forceinline__ unsigned pack_h2(float f0, float f1) {
    __half2 h = __floats2half2_rn(f0, f1);
    return *(unsigned*)&h;
}

// One-time: convert W into m16n8k16 fp16 B-fragment order.
__global__ void k_wprep(const float* __restrict__ W) {
    int i = blockIdx.x * blockDim.x + threadIdx.x;
    if (i >= 16 * 4 * 32) return;
    int lane = i & 31;
    int ktp = (i >> 5) & 3;
    int nt = i >> 7;
    int g = lane >> 2, t = lane & 3;
    int nc = nt * 8 + g;
    int k0 = ktp * 32 + 2 * t;
    uint4 o;
    o.x = pack_h2(W[(k0)      * F + nc], W[(k0 + 1)  * F + nc]);
    o.y = pack_h2(W[(k0 + 8)  * F + nc], W[(k0 + 9)  * F + nc]);
    o.z = pack_h2(W[(k0 + 16) * F + nc], W[(k0 + 17) * F + nc]);
    o.w = pack_h2(W[(k0 + 24) * F + nc], W[(k0 + 25) * F + nc]);
    g_wf16[i] = o;
}

// GEMM via HMMA fp16 (m16n8k16): g_h16 = x @ W (UNscaled), fp16 out.
// No edge-data dependency -> runs from t=0 parallel to the full CSR build.
__global__ __launch_bounds__(256, 3) void k_gemm(const float* __restrict__ x,
                                                 int n) {
    const int tid = threadIdx.x;
    const int warp = tid >> 5, lane = tid & 31;
    const int g = lane >> 2, t = lane & 3;
    const int row0 = blockIdx.x * 128;

    const int rA = row0 + warp * 16 + g;
    const int rB = rA + 8;
    const float* xA = x + (size_t)((rA < n) ? rA : (n - 1)) * F;
    const float* xB = x + (size_t)((rB < n) ? rB : (n - 1)) * F;

    unsigned a[8][4];
#pragma unroll
    for (int kt = 0; kt < 8; kt++) {
        int k0 = kt * 16 + 2 * t;
        float2 vA0 = *(const float2*)(xA + k0);
        float2 vB0 = *(const float2*)(xB + k0);
        float2 vA1 = *(const float2*)(xA + k0 + 8);
        float2 vB1 = *(const float2*)(xB + k0 + 8);
        a[kt][0] = pack_h2(vA0.x, vA0.y);
        a[kt][1] = pack_h2(vB0.x, vB0.y);
        a[kt][2] = pack_h2(vA1.x, vA1.y);
        a[kt][3] = pack_h2(vB1.x, vB1.y);
    }

    const uint4* wf = g_wf16;
#pragma unroll 4
    for (int nt = 0; nt < 16; nt++) {
        float d0 = 0.f, d1 = 0.f, d2 = 0.f, d3 = 0.f;
#pragma unroll
        for (int ktp = 0; ktp < 4; ktp++) {
            uint4 bf = wf[(nt * 4 + ktp) * 32 + lane];
            asm volatile(
                "mma.sync.aligned.m16n8k16.row.col.f32.f16.f16.f32 "
                "{%0,%1,%2,%3}, {%4,%5,%6,%7}, {%8,%9}, {%0,%1,%2,%3};"
                : "+f"(d0), "+f"(d1), "+f"(d2), "+f"(d3)
                : "r"(a[2 * ktp][0]), "r"(a[2 * ktp][1]),
                  "r"(a[2 * ktp][2]), "r"(a[2 * ktp][3]),
                  "r"(bf.x), "r"(bf.y));
            asm volatile(
                "mma.sync.aligned.m16n8k16.row.col.f32.f16.f16.f32 "
                "{%0,%1,%2,%3}, {%4,%5,%6,%7}, {%8,%9}, {%0,%1,%2,%3};"
                : "+f"(d0), "+f"(d1), "+f"(d2), "+f"(d3)
                : "r"(a[2 * ktp + 1][0]), "r"(a[2 * ktp + 1][1]),
                  "r"(a[2 * ktp + 1][2]), "r"(a[2 * ktp + 1][3]),
                  "r"(bf.z), "r"(bf.w));
        }
        if (rA < n)
            g_h16[(size_t)rA * 64 + nt * 4 + t] = __floats2half2_rn(d0, d1);
        if (rB < n)
            g_h16[(size_t)rB * 64 + nt * 4 + t] = __floats2half2_rn(d2, d3);
    }
}

// ---------------------------------------------------------------------------
// Aggregate: one warp per dst node; uint2/lane fp16 gathers (256B rows),
// warp-uniform scalar coef loads (unaligned-safe), fp32 FMA accum, unroll 8.
// out = (sum_e h[s_e]*dinv[s_e] + h[node]*dd) * dd + b
__global__ __launch_bounds__(256) void k_agg(const float* __restrict__ bias,
                                             float* __restrict__ out, int n) {
    int node = blockIdx.x * 8 + (threadIdx.x >> 5);
    if (node >= n) return;
    int lane = threadIdx.x & 31;

    const uint2* h = (const uint2*)g_h16;  // 4 halfs / lane / row
    float dd = g_dinv[node];

    float4 acc;
    {
        uint2 sv = h[(size_t)node * 32 + lane];  // self-loop: h[node]*dd
        float2 f0 = __half22float2(*(__half2*)&sv.x);
        float2 f1 = __half22float2(*(__half2*)&sv.y);
        acc.x = f0.x * dd; acc.y = f0.y * dd;
        acc.z = f1.x * dd; acc.w = f1.y * dd;
    }

    int j = g_start[node];
    int end = j + g_cnt[node];

    for (; j + 7 < end; j += 8) {
        int s0 = g_esrc[j],     s1 = g_esrc[j + 1];
        int s2 = g_esrc[j + 2], s3 = g_esrc[j + 3];
        int s4 = g_esrc[j + 4], s5 = g_esrc[j + 5];
        int s6 = g_esrc[j + 6], s7 = g_esrc[j + 7];
        float c0 = g_ecoef[j],     c1 = g_ecoef[j + 1];
        float c2 = g_ecoef[j + 2], c3 = g_ecoef[j + 3];
        float c4 = g_ecoef[j + 4], c5 = g_ecoef[j + 5];
        float c6 = g_ecoef[j + 6], c7 = g_ecoef[j + 7];
        uint2 v0 = h[(size_t)s0 * 32 + lane];
        uint2 v1 = h[(size_t)s1 * 32 + lane];
        uint2 v2 = h[(size_t)s2 * 32 + lane];
        uint2 v3 = h[(size_t)s3 * 32 + lane];
        uint2 v4 = h[(size_t)s4 * 32 + lane];
        uint2 v5 = h[(size_t)s5 * 32 + lane];
        uint2 v6 = h[(size_t)s6 * 32 + lane];
        uint2 v7 = h[(size_t)s7 * 32 + lane];
#pragma unroll
        for (int k = 0; k < 8; k++) {
            uint2 v = (k == 0) ? v0 : (k == 1) ? v1 : (k == 2) ? v2 :
                      (k == 3) ? v3 : (k == 4) ? v4 : (k == 5) ? v5 :
                      (k == 6) ? v6 : v7;
            float c = (k == 0) ? c0 : (k == 1) ? c1 : (k == 2) ? c2 :
                      (k == 3) ? c3 : (k == 4) ? c4 : (k == 5) ? c5 :
                      (k == 6) ? c6 : c7;
            float2 f0 = __half22float2(*(__half2*)&v.x);
            float2 f1 = __half22float2(*(__half2*)&v.y);
            acc.x += f0.x * c; acc.y += f0.y * c;
            acc.z += f1.x * c; acc.w += f1.y * c;
        }
    }
    for (; j < end; j++) {
        int s = g_esrc[j];
        float c = g_ecoef[j];
        uint2 v = h[(size_t)s * 32 + lane];
        float2 f0 = __half22float2(*(__half2*)&v.x);
        float2 f1 = __half22float2(*(__half2*)&v.y);
        acc.x += f0.x * c; acc.y += f0.y * c;
        acc.z += f1.x * c; acc.w += f1.y * c;
    }

    float4 bv = ((const float4*)bias)[lane];
    float4 o;
    o.x = acc.x * dd + bv.x;
    o.y = acc.y * dd + bv.y;
    o.z = acc.z * dd + bv.z;
    o.w = acc.w * dd + bv.w;
    ((float4*)out)[(size_t)node * 32 + lane] = o;
}

// ---------------------------------------------------------------------------
// Launch DAG:
//   [B: wprep -> gemm]                               (side stream, t=0)
//   [A: zero -> hist -> scan1 -> scan3 -> fill]       (main stream)
//   join(A, B) -> agg
extern "C" void kernel_launch(void* const* d_in, const int* in_sizes, int n_in,
                              void* d_out, int out_size) {
    const float* x  = (const float*)d_in[0];
    const int*   ei = (const int*)d_in[1];
    const float* W  = (const float*)d_in[3];
    const float* b  = (const float*)d_in[4];
    float* out = (float*)d_out;

    int n = in_sizes[0] / F;
    int e = in_sizes[1] / 2;
    const int* src = ei;
    const int* dst = ei + e;

    int nblk = (n + SCAN_CHUNK - 1) / SCAN_CHUNK;

    // One-time host-side setup on the (uncaptured) correctness call.
    static cudaStream_t s2 = nullptr;
    static cudaEvent_t evRoot = nullptr, evGemm = nullptr;
    if (s2 == nullptr) {
        cudaStreamCreateWithFlags(&s2, cudaStreamNonBlocking);
        cudaEventCreateWithFlags(&evRoot, cudaEventDisableTiming);
        cudaEventCreateWithFlags(&evGemm, cudaEventDisableTiming);
    }

    // fork: side stream roots at capture begin
    cudaEventRecord(evRoot, 0);
    cudaStreamWaitEvent(s2, evRoot, 0);

    // dense chain (fully independent of edge data)
    k_wprep<<<8, 256, 0, s2>>>(W);
    k_gemm <<<(n + 127) / 128, 256, 0, s2>>>(x, n);
    cudaEventRecord(evGemm, s2);

    // edge/CSR chain
    k_zero <<<(n + 255) / 256, 256>>>(n);
    k_hist <<<(e / 4 + 255) / 256, 256>>>(dst, e);
    k_scan1<<<nblk, SCAN_CHUNK>>>(n);
    k_scan3<<<nblk, SCAN_CHUNK>>>(n, nblk);
    k_fill <<<(e + 255) / 256, 256>>>(src, dst, e);

    // join
    cudaStreamWaitEvent(0, evGemm, 0);
    k_agg  <<<(n + 7) / 8, 256>>>(b, out, n);
}